// round 3
// baseline (speedup 1.0000x reference)
#include <cuda_runtime.h>

#define KCLS 256
#define WARPS_PER_BLOCK 8
#define THREADS (WARPS_PER_BLOCK * 32)
#define ROWS_PER_WARP 2

__device__ __forceinline__ float ex2f(float a) {
    float r; asm("ex2.approx.f32 %0, %1;" : "=f"(r) : "f"(a)); return r;
}
__device__ __forceinline__ float rcpf(float a) {
    float r; asm("rcp.approx.f32 %0, %1;" : "=f"(r) : "f"(a)); return r;
}

__global__ __launch_bounds__(THREADS)
void dbf_kernel(const int* __restrict__ data,
                const float* __restrict__ t,
                const float4* __restrict__ noise,
                float4* __restrict__ out,
                int nrows)
{
    __shared__ __align__(16) float sg[KCLS];
    __shared__ __align__(16) float sh[KCLS];

    const int tid  = threadIdx.x;
    const int lane = tid & 31;
    const int warp = tid >> 5;

    // Closed-form Cholesky of C0 = (K+0.001) I - 11^T:
    //   T_k = a/(k-a), g_k = sqrt(a+T_k), h_k = T_k/g_k, a = K+0.001
    {
        const float ALPHA = 256.001f;
        float kf = (float)tid;
        float T  = ALPHA / (kf - ALPHA);
        float g  = sqrtf(ALPHA + T);
        sg[tid] = g;
        sh[tid] = T / g;
    }
    __syncthreads();

    const int rowbase = (blockIdx.x * WARPS_PER_BLOCK + warp) * ROWS_PER_WARP;
    if (rowbase >= nrows) return;

    const int kbase = lane * 8;

    // g/h slice for this lane's 8 classes (shared across both rows)
    float4 g0 = *(const float4*)&sg[kbase];
    float4 g1 = *(const float4*)&sg[kbase + 4];
    float4 h0 = *(const float4*)&sh[kbase];
    float4 h1 = *(const float4*)&sh[kbase + 4];
    const float g[8] = {g0.x, g0.y, g0.z, g0.w, g1.x, g1.y, g1.z, g1.w};
    const float h[8] = {h0.x, h0.y, h0.z, h0.w, h1.x, h1.y, h1.z, h1.w};

    const float L2E = 1.4426950408889634f;

    float v[ROWS_PER_WARP][8];
    float sb2[ROWS_PER_WARP];    // sb * log2(e)
    float kb2[ROWS_PER_WARP];    // K * beta * log2(e)
    int   xcls[ROWS_PER_WARP];
    bool  lob[ROWS_PER_WARP];
    int   rowi[ROWS_PER_WARP];

    #pragma unroll
    for (int r = 0; r < ROWS_PER_WARP; r++) {
        int row = rowbase + r;
        rowi[r] = row;
        int rl = row < nrows ? row : nrows - 1;     // clamp (tail safety)
        float tv = __ldg(t + rl);
        xcls[r]  = __ldg(data + rl);
        float sb = fminf(tv, 1.0f - 1e-6f);
        lob[r]   = (sb < 1e-10f);
        sb       = fmaxf(sb, 1e-10f);
        sb2[r]   = sb * L2E;
        kb2[r]   = 256.0f * (sb * sb) * L2E;
        const float4* nrow = noise + (size_t)rl * (KCLS / 4);
        float4 a = __ldg(nrow + lane * 2 + 0);
        float4 b = __ldg(nrow + lane * 2 + 1);
        v[r][0]=a.x; v[r][1]=a.y; v[r][2]=a.z; v[r][3]=a.w;
        v[r][4]=b.x; v[r][5]=b.y; v[r][6]=b.z; v[r][7]=b.w;
    }

    // local exclusive prefix of h*v (both rows interleaved for ILP)
    float p[ROWS_PER_WARP][8];
    float run0 = 0.0f, run1 = 0.0f;
    #pragma unroll
    for (int i = 0; i < 8; i++) {
        p[0][i] = run0;  run0 = fmaf(h[i], v[0][i], run0);
        p[1][i] = run1;  run1 = fmaf(h[i], v[1][i], run1);
    }
    // warp inclusive scan of lane totals, interleaved
    float inc0 = run0, inc1 = run1;
    #pragma unroll
    for (int d = 1; d < 32; d <<= 1) {
        float a0 = __shfl_up_sync(0xFFFFFFFFu, inc0, d);
        float a1 = __shfl_up_sync(0xFFFFFFFFu, inc1, d);
        if (lane >= d) { inc0 += a0; inc1 += a1; }
    }
    float ex0 = __shfl_up_sync(0xFFFFFFFFu, inc0, 1);
    float ex1 = __shfl_up_sync(0xFFFFFFFFu, inc1, 1);
    if (lane == 0) { ex0 = 0.0f; ex1 = 0.0f; }
    float excl[ROWS_PER_WARP] = {ex0, ex1};

    // logits in log2 domain; common -beta term dropped (softmax-invariant):
    //   l_k = sb2 * (g_k v_k + prefix_k) + (k==x ? K*beta*log2e : 0)
    float lg[ROWS_PER_WARP][8];
    float mx[ROWS_PER_WARP];
    #pragma unroll
    for (int r = 0; r < ROWS_PER_WARP; r++) {
        float m = -3.4e38f;
        #pragma unroll
        for (int i = 0; i < 8; i++) {
            float y = fmaf(g[i], v[r][i], p[r][i] + excl[r]);
            float l = fmaf(sb2[r], y, (kbase + i == xcls[r]) ? kb2[r] : 0.0f);
            lg[r][i] = l;
            m = fmaxf(m, l);
        }
        mx[r] = m;
    }
    // warp max via butterfly, both rows interleaved
    #pragma unroll
    for (int d = 16; d >= 1; d >>= 1) {
        float a0 = __shfl_xor_sync(0xFFFFFFFFu, mx[0], d);
        float a1 = __shfl_xor_sync(0xFFFFFFFFu, mx[1], d);
        mx[0] = fmaxf(mx[0], a0);
        mx[1] = fmaxf(mx[1], a1);
    }

    // exp2 + sum
    float e[ROWS_PER_WARP][8];
    float s[ROWS_PER_WARP];
    #pragma unroll
    for (int r = 0; r < ROWS_PER_WARP; r++) {
        float acc = 0.0f;
        #pragma unroll
        for (int i = 0; i < 8; i++) {
            e[r][i] = ex2f(lg[r][i] - mx[r]);
            acc += e[r][i];
        }
        s[r] = acc;
    }
    // warp sum via butterfly, interleaved
    #pragma unroll
    for (int d = 16; d >= 1; d >>= 1) {
        float a0 = __shfl_xor_sync(0xFFFFFFFFu, s[0], d);
        float a1 = __shfl_xor_sync(0xFFFFFFFFu, s[1], d);
        s[0] += a0;
        s[1] += a1;
    }

    #pragma unroll
    for (int r = 0; r < ROWS_PER_WARP; r++) {
        if (rowi[r] >= nrows) continue;
        float4* orow = out + (size_t)rowi[r] * (KCLS / 4);
        if (lob[r]) {
            const float uni = 1.0f / 256.0f;
            float4 u = make_float4(uni, uni, uni, uni);
            orow[lane * 2 + 0] = u;
            orow[lane * 2 + 1] = u;
        } else {
            float rr = rcpf(s[r]);
            float4 w0 = make_float4(e[r][0]*rr, e[r][1]*rr, e[r][2]*rr, e[r][3]*rr);
            float4 w1 = make_float4(e[r][4]*rr, e[r][5]*rr, e[r][6]*rr, e[r][7]*rr);
            orow[lane * 2 + 0] = w0;
            orow[lane * 2 + 1] = w1;
        }
    }
}

extern "C" void kernel_launch(void* const* d_in, const int* in_sizes, int n_in,
                              void* d_out, int out_size)
{
    const int*    data  = (const int*)d_in[0];
    const float*  t     = (const float*)d_in[1];
    const float4* noise = (const float4*)d_in[2];
    float4*       out   = (float4*)d_out;

    const int nrows = in_sizes[0];     // B*S = 16384
    const int rows_per_block = WARPS_PER_BLOCK * ROWS_PER_WARP;
    const int blocks = (nrows + rows_per_block - 1) / rows_per_block;
    dbf_kernel<<<blocks, THREADS>>>(data, t, noise, out, nrows);
}